// round 7
// baseline (speedup 1.0000x reference)
#include <cuda_runtime.h>

// ----------------------------------------------------------------------------
// RNNDecoder: 3-layer GRU (H=128), T=256, B=1024, fc head (out=2).
//
// R6 = R5 (K-split, 128 CTAs x 256 threads) with f32x2 lanes repacked over
// k-pairs (was batch-pairs): the per-weight dup2 MOV (768/thread/cell of
// fma/alu-pipe contention) is eliminated; packed weights come straight from
// the LDG.128 as ulonglong2.
//   - Activations live in smem as [b][k] so (x[b][k],x[b][k+1]) is a natural
//     lane pair; all activation LDS remain warp-broadcast.
//   - acc[3][2][8] ull lanes = (even-k, odd-k) partial sums; lane-reduced
//     before the cross-K-half exchange (12 ST.64/LD.64, conflict-free).
//   - All accumulator indices compile-time (unrolled loops + templates).
// ----------------------------------------------------------------------------

namespace {
constexpr int LAYERS = 3;
constexpr int H      = 128;
constexpr int G3     = 3 * H;
constexpr int T      = 256;
constexpr int BC     = 8;
constexpr int NTHR   = 256;
constexpr int NBLK   = 128;        // 1024 / BC
constexpr int KKH    = 16;         // float4 K-chunks per K-half
}

typedef unsigned long long ull;

// Transposed weights: [l][kkp][ga(ih_r,ih_z,ih_n,hh_r,hh_z,hh_n)][tid]
// as ulonglong2 (= float4 bytes); tid = grp*128 + u -> (unit u, K-half grp).
__device__ ulonglong2 g_wt[LAYERS * KKH * 6 * NTHR];

__global__ void prep_kernel(const float* __restrict__ wih,
                            const float* __restrict__ whh) {
  int idx = blockIdx.x * blockDim.x + threadIdx.x;
  if (idx >= LAYERS * KKH * 6 * NTHR) return;
  int t   = idx % NTHR;
  int ga  = (idx / NTHR) % 6;
  int kkp = (idx / (NTHR * 6)) % KKH;
  int l   = idx / (NTHR * 6 * KKH);
  int g   = ga % 3, arr = ga / 3;
  int u   = t & 127, grp = t >> 7;
  int k4  = grp * KKH + kkp;
  const float* src = (arr ? whh : wih) + (l * G3 + g * 128 + u) * H + k4 * 4;
  g_wt[idx] = *reinterpret_cast<const ulonglong2*>(src);
}

__device__ __forceinline__ void ffma2(ull& a, ull w, ull x) {
  asm("fma.rn.f32x2 %0, %1, %2, %0;" : "+l"(a) : "l"(w), "l"(x));
}
__device__ __forceinline__ float2 unpk(ull v) {
  float lo, hi;
  asm("mov.b64 {%0, %1}, %2;" : "=f"(lo), "=f"(hi) : "l"(v));
  return make_float2(lo, hi);
}
__device__ __forceinline__ ull pack2(float lo, float hi) {
  ull r;
  asm("mov.b64 %0, {%1, %2};" : "=l"(r) : "f"(lo), "f"(hi));
  return r;
}
__device__ __forceinline__ float lanesum(ull v) {
  float2 f = unpk(v);
  return f.x + f.y;
}
__device__ __forceinline__ float sigm(float x) {
  return __fdividef(1.0f, 1.0f + __expf(-x));
}
__device__ __forceinline__ float tanh_fast(float v) {
  float a = fabsf(v);
  float e = __expf(-2.0f * a);
  float r = __fdividef(1.0f - e, 1.0f + e);
  return copysignf(r, v);
}

// Store lane-reduced partials (batch-half B..B+3) for the partner group.
template <int B>
__device__ __forceinline__ void store_red(ull* __restrict__ dst,
                                          const float (&rs)[3][2][8], int u) {
#pragma unroll
  for (int g = 0; g < 3; g++)
#pragma unroll
    for (int a = 0; a < 2; a++) {
      dst[((g * 2 + a) * 2 + 0) * 128 + u] = pack2(rs[g][a][B],     rs[g][a][B + 1]);
      dst[((g * 2 + a) * 2 + 1) * 128 + u] = pack2(rs[g][a][B + 2], rs[g][a][B + 3]);
    }
}

// Add partner partials for batch-half B..B+3 and run the GRU gate combine.
template <int B>
__device__ __forceinline__ void combine4(float (&rs)[3][2][8],
                                         const ull* __restrict__ src, int u,
                                         float brz_r, float brz_z,
                                         float bn_x, float bn_h,
                                         float* __restrict__ hl,
                                         float* __restrict__ sx) {
#pragma unroll
  for (int g = 0; g < 3; g++)
#pragma unroll
    for (int a = 0; a < 2; a++)
#pragma unroll
      for (int p = 0; p < 2; p++) {
        float2 f = unpk(src[((g * 2 + a) * 2 + p) * 128 + u]);
        rs[g][a][B + 2 * p]     += f.x;
        rs[g][a][B + 2 * p + 1] += f.y;
      }
#pragma unroll
  for (int bb = 0; bb < 4; bb++) {
    const int b = B + bb;
    float r = sigm(rs[0][0][b] + rs[0][1][b] + brz_r);
    float z = sigm(rs[1][0][b] + rs[1][1][b] + brz_z);
    float n = tanh_fast(rs[2][0][b] + bn_x + r * (rs[2][1][b] + bn_h));
    float hp = hl[b * 128 + u];
    float hn = fmaf(z, hp - n, n);        // (1-z)*n + z*h
    hl[b * 128 + u] = hn;
    sx[b * 128 + u] = hn;
  }
}

__global__ void __launch_bounds__(NTHR, 1)
gru_kernel(const float* __restrict__ hiddens,
           const float* __restrict__ b_ih,
           const float* __restrict__ b_hh,
           const float* __restrict__ fc_w,
           const float* __restrict__ fc_b,
           float* __restrict__ out) {
  __shared__ __align__(16) float s_x[BC * H];            // [b][k]
  __shared__ __align__(16) float s_h[LAYERS * BC * H];   // [l][b][k]
  __shared__ __align__(16) ull   s_pA[12 * 128];         // grp1 -> grp0 (b0..3)
  __shared__ __align__(16) ull   s_pB[12 * 128];         // grp0 -> grp1 (b4..7)
  __shared__ float s_fcw[2 * H];
  __shared__ float s_fcb[2];

  const int tid = threadIdx.x;
  const int u   = tid & 127;
  const int grp = tid >> 7;
  const int b0  = blockIdx.x * BC;

  // Biases for hidden unit u (r,z summed; n split).
  float brz_r[LAYERS], brz_z[LAYERS], bn_x[LAYERS], bn_h[LAYERS];
#pragma unroll
  for (int l = 0; l < LAYERS; l++) {
    brz_r[l] = b_ih[l * G3 + u]       + b_hh[l * G3 + u];
    brz_z[l] = b_ih[l * G3 + 128 + u] + b_hh[l * G3 + 128 + u];
    bn_x[l]  = b_ih[l * G3 + 256 + u];
    bn_h[l]  = b_hh[l * G3 + 256 + u];
  }
  s_fcw[tid] = fc_w[tid];
  if (tid < 2) s_fcb[tid] = fc_b[tid];

  // h init: hiddens[b][l][k] -> s_h[l][b][k] (coalesced per 128-float row).
  for (int i = tid; i < LAYERS * BC * H; i += NTHR) {
    int l = i >> 10, rem = i & 1023, b = rem >> 7, k = rem & 127;
    s_h[i] = hiddens[(b0 + b) * (LAYERS * H) + l * H + k];
  }
  for (int i = tid; i < BC * H; i += NTHR) s_x[i] = 0.0f;
  __syncthreads();

  for (int t = 0; t < T; t++) {
#pragma unroll 1
    for (int l = 0; l < LAYERS; l++) {
      const float* __restrict__  xb = s_x + grp * 64;
      float* __restrict__        hl = s_h + l * (BC * H);
      const float* __restrict__  hb = hl + grp * 64;
      const ulonglong2* __restrict__ wp = g_wt + l * (KKH * 6 * NTHR) + tid;

      // acc[g][arr][b] lanes = (even-k, odd-k) partial sums.
      ull acc[3][2][8];
#pragma unroll
      for (int g = 0; g < 3; g++)
#pragma unroll
        for (int a = 0; a < 2; a++)
#pragma unroll
          for (int b = 0; b < 8; b++) acc[g][a][b] = 0ull;

      ulonglong2 wv[6], wn[6];
#pragma unroll
      for (int i = 0; i < 6; i++) wn[i] = wp[i * NTHR];

#pragma unroll 2
      for (int kkp = 0; kkp < KKH; kkp++) {
#pragma unroll
        for (int i = 0; i < 6; i++) {
          wv[i] = wn[i];
          wn[i] = wp[(((kkp + 1) & (KKH - 1)) * 6 + i) * NTHR];
        }
#pragma unroll
        for (int b = 0; b < 8; b++) {
          // 4 consecutive k for batch b: one broadcast LDS.128 per array.
          ulonglong2 xv = *reinterpret_cast<const ulonglong2*>(
              xb + b * 128 + kkp * 4);
          ulonglong2 hv = *reinterpret_cast<const ulonglong2*>(
              hb + b * 128 + kkp * 4);
#pragma unroll
          for (int g = 0; g < 3; g++) {
            ffma2(acc[g][0][b], wv[g].x, xv.x);       // W_ih, k pair 0
            ffma2(acc[g][0][b], wv[g].y, xv.y);       //       k pair 1
            ffma2(acc[g][1][b], wv[3 + g].x, hv.x);   // W_hh
            ffma2(acc[g][1][b], wv[3 + g].y, hv.y);
          }
        }
      }

      // Lane-reduce (even+odd k) to scalars.
      float rs[3][2][8];
#pragma unroll
      for (int g = 0; g < 3; g++)
#pragma unroll
        for (int a = 0; a < 2; a++)
#pragma unroll
          for (int b = 0; b < 8; b++) rs[g][a][b] = lanesum(acc[g][a][b]);

      // Exchange: grp0 gives b4..7 (for grp1), grp1 gives b0..3 (for grp0).
      if (grp == 0) store_red<4>(s_pB, rs, u);
      else          store_red<0>(s_pA, rs, u);
      __syncthreads();

      if (grp == 0)
        combine4<0>(rs, s_pA, u, brz_r[l], brz_z[l], bn_x[l], bn_h[l], hl, s_x);
      else
        combine4<4>(rs, s_pB, u, brz_r[l], brz_z[l], bn_x[l], bn_h[l], hl, s_x);
      __syncthreads();

      // fc head on top-layer output: 16 outputs (2 out x 8 batch) x 16 lanes.
      if (l == 2) {
        int oid = tid >> 4, s = tid & 15;
        int o = oid & 1, b = oid >> 1;
        float p = 0.0f;
#pragma unroll
        for (int m = 0; m < 8; m++)
          p = fmaf(s_fcw[o * H + s * 8 + m], s_x[b * 128 + s * 8 + m], p);
        p += __shfl_down_sync(0xffffffffu, p, 8, 16);
        p += __shfl_down_sync(0xffffffffu, p, 4, 16);
        p += __shfl_down_sync(0xffffffffu, p, 2, 16);
        p += __shfl_down_sync(0xffffffffu, p, 1, 16);
        if (s == 0) out[((b0 + b) * T + t) * 2 + o] = p + s_fcb[o];
      }
      // fc reads of s_x complete before the next cell's combine rewrites s_x
      // (that rewrite sits behind the next cell's exchange __syncthreads()).
    }
  }
}

extern "C" void kernel_launch(void* const* d_in, const int* in_sizes, int n_in,
                              void* d_out, int out_size) {
  (void)in_sizes; (void)n_in; (void)out_size;
  const float* hiddens = (const float*)d_in[0];
  const float* W_ih    = (const float*)d_in[1];
  const float* W_hh    = (const float*)d_in[2];
  const float* b_ih    = (const float*)d_in[3];
  const float* b_hh    = (const float*)d_in[4];
  const float* fc_w    = (const float*)d_in[5];
  const float* fc_b    = (const float*)d_in[6];
  float* out = (float*)d_out;

  const int prep_elems = LAYERS * KKH * 6 * NTHR;
  prep_kernel<<<(prep_elems + 255) / 256, 256>>>(W_ih, W_hh);
  gru_kernel<<<NBLK, NTHR>>>(hiddens, b_ih, b_hh, fc_w, fc_b, out);
}

// round 8
// speedup vs baseline: 1.0362x; 1.0362x over previous
#include <cuda_runtime.h>

// ----------------------------------------------------------------------------
// RNNDecoder: 3-layer GRU (H=128), T=256, B=1024, fc head (out=2).
//
// R7: 128 CTAs x 512 threads, 4-way K-split.
//   - Thread (grp,u): u = hidden unit (r,z,n rows), grp = K-quarter (32 k).
//     768 FFMA2/thread/cell, 4 warps per SMSP -> latency hidden by TLP.
//   - Batch-pair f32x2 packing (acc[3][2][4] = 48 regs; dup2 MOVs go to the
//     alu pipe, proven harmless in R6). Single-buffered weights.
//   - Flat 4-way reduce: r,z pre-summed across arrays in-reg; each group
//     stores 4 ull per non-owned pair; owner adds 3 contributions.
//     Dynamic smem (66.6KB) for the exchange table; 2 barriers/cell.
//   - Weights pre-transposed for 2KB-coalesced warp LDG.
// ----------------------------------------------------------------------------

namespace {
constexpr int LAYERS = 3;
constexpr int H      = 128;
constexpr int G3     = 3 * H;
constexpr int T      = 256;
constexpr int BC     = 8;
constexpr int NTHR   = 512;
constexpr int NBLK   = 128;        // 1024 / BC
constexpr int KKQ    = 8;          // float4 K-chunks per K-quarter

// dynamic smem layout (bytes)
constexpr int SMEM_X   = 0;        // float[1024]  s_x  [k][b]
constexpr int SMEM_H   = 4096;     // float[3072]  s_h  [l][k][b]
constexpr int SMEM_P   = 16384;    // ull[6144]    exchange [q][c][v][u]
constexpr int SMEM_FCW = 65536;    // float[256]
constexpr int SMEM_FCB = 66560;    // float[2]
constexpr int SMEM_TOTAL = 66576;
}

typedef unsigned long long ull;

// Transposed weights: [l][kkp][ga(ih_r,ih_z,ih_n,hh_r,hh_z,hh_n)][tid] float4,
// tid = grp*128 + u -> (unit u, K-quarter grp).
__device__ float4 g_wt[LAYERS * KKQ * 6 * NTHR];

__global__ void prep_kernel(const float* __restrict__ wih,
                            const float* __restrict__ whh) {
  int idx = blockIdx.x * blockDim.x + threadIdx.x;
  if (idx >= LAYERS * KKQ * 6 * NTHR) return;
  int t   = idx % NTHR;
  int ga  = (idx / NTHR) % 6;
  int kkp = (idx / (NTHR * 6)) % KKQ;
  int l   = idx / (NTHR * 6 * KKQ);
  int g   = ga % 3, arr = ga / 3;
  int u   = t & 127, grp = t >> 7;
  int k4  = grp * KKQ + kkp;
  const float* src = (arr ? whh : wih) + (l * G3 + g * 128 + u) * H + k4 * 4;
  g_wt[idx] = *reinterpret_cast<const float4*>(src);
}

__device__ __forceinline__ void ffma2(ull& a, ull w, ull x) {
  asm("fma.rn.f32x2 %0, %1, %2, %0;" : "+l"(a) : "l"(w), "l"(x));
}
__device__ __forceinline__ void fadd2(ull& a, ull b) {
  asm("add.rn.f32x2 %0, %0, %1;" : "+l"(a) : "l"(b));
}
__device__ __forceinline__ ull dup2(float w) {
  ull r;
  asm("mov.b64 %0, {%1, %1};" : "=l"(r) : "f"(w));
  return r;
}
__device__ __forceinline__ float2 unpk(ull v) {
  float lo, hi;
  asm("mov.b64 {%0, %1}, %2;" : "=f"(lo), "=f"(hi) : "l"(v));
  return make_float2(lo, hi);
}
__device__ __forceinline__ ull pack2(float lo, float hi) {
  ull r;
  asm("mov.b64 %0, {%1, %2};" : "=l"(r) : "f"(lo), "f"(hi));
  return r;
}
__device__ __forceinline__ float sigm(float x) {
  return __fdividef(1.0f, 1.0f + __expf(-x));
}
__device__ __forceinline__ float tanh_fast(float v) {
  float a = fabsf(v);
  float e = __expf(-2.0f * a);
  float r = __fdividef(1.0f - e, 1.0f + e);
  return copysignf(r, v);
}
__device__ __forceinline__ float comp(const float4& v, int e) {
  return e == 0 ? v.x : e == 1 ? v.y : e == 2 ? v.z : v.w;
}

// Combine batch-pair Q: add 3 partner contributions, run GRU gate math,
// write new hidden state. Q compile-time -> callers give constant acc values.
template <int Q>
__device__ __forceinline__ void combine_pair(ull r2, ull z2, ull nx2, ull nh2,
                                             const ull* __restrict__ sp, int u,
                                             float brz_r, float brz_z,
                                             float bn_x, float bn_h,
                                             float* __restrict__ hl,
                                             float* __restrict__ sx) {
#pragma unroll
  for (int c = 0; c < 3; c++) {
    const ull* base = sp + (Q * 3 + c) * 4 * 128 + u;
    fadd2(r2,  base[0]);
    fadd2(z2,  base[128]);
    fadd2(nx2, base[256]);
    fadd2(nh2, base[384]);
  }
  float2 rr = unpk(r2), zz = unpk(z2), xx = unpk(nx2), hh = unpk(nh2);
  float hp0 = hl[u * 8 + 2 * Q], hp1 = hl[u * 8 + 2 * Q + 1];
  float r0 = sigm(rr.x + brz_r), z0 = sigm(zz.x + brz_z);
  float n0 = tanh_fast(xx.x + bn_x + r0 * (hh.x + bn_h));
  float h0 = fmaf(z0, hp0 - n0, n0);
  float r1 = sigm(rr.y + brz_r), z1 = sigm(zz.y + brz_z);
  float n1 = tanh_fast(xx.y + bn_x + r1 * (hh.y + bn_h));
  float h1 = fmaf(z1, hp1 - n1, n1);
  ull o = pack2(h0, h1);
  *reinterpret_cast<ull*>(hl + u * 8 + 2 * Q) = o;
  *reinterpret_cast<ull*>(sx + u * 8 + 2 * Q) = o;
}

__global__ void __launch_bounds__(NTHR, 1)
gru_kernel(const float* __restrict__ hiddens,
           const float* __restrict__ b_ih,
           const float* __restrict__ b_hh,
           const float* __restrict__ fc_w,
           const float* __restrict__ fc_b,
           float* __restrict__ out) {
  extern __shared__ __align__(16) char dsm[];
  float* s_x   = reinterpret_cast<float*>(dsm + SMEM_X);
  float* s_h   = reinterpret_cast<float*>(dsm + SMEM_H);
  ull*   s_p   = reinterpret_cast<ull*>(dsm + SMEM_P);
  float* s_fcw = reinterpret_cast<float*>(dsm + SMEM_FCW);
  float* s_fcb = reinterpret_cast<float*>(dsm + SMEM_FCB);

  const int tid = threadIdx.x;
  const int u   = tid & 127;
  const int grp = tid >> 7;
  const int b0  = blockIdx.x * BC;

  // Biases for hidden unit u (r,z summed; n split).
  float brz_r[LAYERS], brz_z[LAYERS], bn_x[LAYERS], bn_h[LAYERS];
#pragma unroll
  for (int l = 0; l < LAYERS; l++) {
    brz_r[l] = b_ih[l * G3 + u]       + b_hh[l * G3 + u];
    brz_z[l] = b_ih[l * G3 + 128 + u] + b_hh[l * G3 + 128 + u];
    bn_x[l]  = b_ih[l * G3 + 256 + u];
    bn_h[l]  = b_hh[l * G3 + 256 + u];
  }
  if (tid < 256) s_fcw[tid] = fc_w[tid];
  if (tid < 2)   s_fcb[tid] = fc_b[tid];

  // h init: hiddens[b][l][k] -> s_h[l][k][b]
  for (int i = tid; i < LAYERS * H * BC; i += NTHR) {
    int l = i >> 10, rem = i & 1023, k = rem >> 3, b = rem & 7;
    s_h[i] = hiddens[(b0 + b) * (LAYERS * H) + l * H + k];
  }
  for (int i = tid; i < H * BC; i += NTHR) s_x[i] = 0.0f;
  __syncthreads();

  for (int t = 0; t < T; t++) {
#pragma unroll 1
    for (int l = 0; l < LAYERS; l++) {
      const float* __restrict__  xb = s_x + grp * 256;         // K-quarter
      float* __restrict__        hl = s_h + l * (H * BC);
      const float* __restrict__  hb = hl + grp * 256;
      const float4* __restrict__ wp = g_wt + l * (KKQ * 6 * NTHR) + tid;

      ull acc[3][2][4];
#pragma unroll
      for (int g = 0; g < 3; g++)
#pragma unroll
        for (int a = 0; a < 2; a++)
#pragma unroll
          for (int q = 0; q < 4; q++) acc[g][a][q] = 0ull;

#pragma unroll 2
      for (int kkp = 0; kkp < KKQ; kkp++) {
        float4 wv[6];
#pragma unroll
        for (int i = 0; i < 6; i++) wv[i] = wp[(kkp * 6 + i) * NTHR];
#pragma unroll
        for (int e = 0; e < 4; e++) {
          int k8 = (kkp * 4 + e) * 8;
          ulonglong2 xv0 = *reinterpret_cast<const ulonglong2*>(xb + k8);
          ulonglong2 xv1 = *reinterpret_cast<const ulonglong2*>(xb + k8 + 4);
          ulonglong2 hv0 = *reinterpret_cast<const ulonglong2*>(hb + k8);
          ulonglong2 hv1 = *reinterpret_cast<const ulonglong2*>(hb + k8 + 4);
#pragma unroll
          for (int g = 0; g < 3; g++) {
            ull dx = dup2(comp(wv[g], e));          // W_ih
            ffma2(acc[g][0][0], dx, xv0.x);
            ffma2(acc[g][0][1], dx, xv0.y);
            ffma2(acc[g][0][2], dx, xv1.x);
            ffma2(acc[g][0][3], dx, xv1.y);
            ull dh = dup2(comp(wv[3 + g], e));      // W_hh
            ffma2(acc[g][1][0], dh, hv0.x);
            ffma2(acc[g][1][1], dh, hv0.y);
            ffma2(acc[g][1][2], dh, hv1.x);
            ffma2(acc[g][1][3], dh, hv1.y);
          }
        }
      }

      // r,z: arrays summed now (only the total matters).
      ull rzr[4], rzz[4];
#pragma unroll
      for (int q = 0; q < 4; q++) {
        rzr[q] = acc[0][0][q]; fadd2(rzr[q], acc[0][1][q]);
        rzz[q] = acc[1][0][q]; fadd2(rzz[q], acc[1][1][q]);
      }

      // Store partials for the 3 pairs this group does not own.
#pragma unroll
      for (int q = 0; q < 4; q++) {
        if (q == grp) continue;                    // runtime guard, const q
        int c = grp - (grp > q ? 1 : 0);
        ull* base = s_p + (q * 3 + c) * 4 * 128 + u;
        base[0]   = rzr[q];
        base[128] = rzz[q];
        base[256] = acc[2][0][q];
        base[384] = acc[2][1][q];
      }
      __syncthreads();

      if (grp == 0)
        combine_pair<0>(rzr[0], rzz[0], acc[2][0][0], acc[2][1][0], s_p, u,
                        brz_r[l], brz_z[l], bn_x[l], bn_h[l], hl, s_x);
      else if (grp == 1)
        combine_pair<1>(rzr[1], rzz[1], acc[2][0][1], acc[2][1][1], s_p, u,
                        brz_r[l], brz_z[l], bn_x[l], bn_h[l], hl, s_x);
      else if (grp == 2)
        combine_pair<2>(rzr[2], rzz[2], acc[2][0][2], acc[2][1][2], s_p, u,
                        brz_r[l], brz_z[l], bn_x[l], bn_h[l], hl, s_x);
      else
        combine_pair<3>(rzr[3], rzz[3], acc[2][0][3], acc[2][1][3], s_p, u,
                        brz_r[l], brz_z[l], bn_x[l], bn_h[l], hl, s_x);
      __syncthreads();

      // fc head on top-layer output: 16 outputs (2 out x 8 batch) x 16 lanes.
      if (l == 2 && tid < 256) {
        int oid = tid >> 4, s = tid & 15;
        int o = oid & 1, b = oid >> 1;
        float p = 0.0f;
#pragma unroll
        for (int m = 0; m < 8; m++)
          p = fmaf(s_fcw[o * H + s * 8 + m], s_x[(s * 8 + m) * 8 + b], p);
        p += __shfl_down_sync(0xffffffffu, p, 8, 16);
        p += __shfl_down_sync(0xffffffffu, p, 4, 16);
        p += __shfl_down_sync(0xffffffffu, p, 2, 16);
        p += __shfl_down_sync(0xffffffffu, p, 1, 16);
        if (s == 0) out[((b0 + b) * T + t) * 2 + o] = p + s_fcb[o];
      }
      // fc reads of s_x finish before the next cell's combine rewrites s_x
      // (that rewrite sits behind the next cell's exchange __syncthreads()).
    }
  }
}

extern "C" void kernel_launch(void* const* d_in, const int* in_sizes, int n_in,
                              void* d_out, int out_size) {
  (void)in_sizes; (void)n_in; (void)out_size;
  const float* hiddens = (const float*)d_in[0];
  const float* W_ih    = (const float*)d_in[1];
  const float* W_hh    = (const float*)d_in[2];
  const float* b_ih    = (const float*)d_in[3];
  const float* b_hh    = (const float*)d_in[4];
  const float* fc_w    = (const float*)d_in[5];
  const float* fc_b    = (const float*)d_in[6];
  float* out = (float*)d_out;

  cudaFuncSetAttribute(gru_kernel, cudaFuncAttributeMaxDynamicSharedMemorySize,
                       SMEM_TOTAL);

  const int prep_elems = LAYERS * KKQ * 6 * NTHR;
  prep_kernel<<<(prep_elems + 255) / 256, 256>>>(W_ih, W_hh);
  gru_kernel<<<NBLK, NTHR, SMEM_TOTAL>>>(hiddens, b_ih, b_hh, fc_w, fc_b, out);
}

// round 9
// speedup vs baseline: 1.0440x; 1.0076x over previous
#include <cuda_runtime.h>

// ----------------------------------------------------------------------------
// RNNDecoder: 3-layer GRU (H=128), T=256, B=1024, fc head (out=2).
//
// R8 = R7 (128 CTAs x 512 threads, 4-way K-split) + weight double-buffering:
// weights for kkp+1 are prefetched while kkp computes, so the ~240-cycle
// L2-hit latency is no longer exposed by bulk-synchronous warps (R7's miss),
// while 4 warps/SMSP keep hiding LDS latency (R5's miss).
//   - Thread (grp,u): u = hidden unit (r,z,n rows), grp = K-quarter (32 k).
//   - Batch-pair f32x2 packing; dup2 MOVs ride the idle alu pipe.
//   - Flat 4-way reduce via dynamic-smem exchange; 2 barriers/cell.
//   - kkp loop fully unrolled; prefetch guard is compile-time.
// ----------------------------------------------------------------------------

namespace {
constexpr int LAYERS = 3;
constexpr int H      = 128;
constexpr int G3     = 3 * H;
constexpr int T      = 256;
constexpr int BC     = 8;
constexpr int NTHR   = 512;
constexpr int NBLK   = 128;        // 1024 / BC
constexpr int KKQ    = 8;          // float4 K-chunks per K-quarter

// dynamic smem layout (bytes)
constexpr int SMEM_X   = 0;        // float[1024]  s_x  [k][b]
constexpr int SMEM_H   = 4096;     // float[3072]  s_h  [l][k][b]
constexpr int SMEM_P   = 16384;    // ull[6144]    exchange [q][c][v][u]
constexpr int SMEM_FCW = 65536;    // float[256]
constexpr int SMEM_FCB = 66560;    // float[2]
constexpr int SMEM_TOTAL = 66576;
}

typedef unsigned long long ull;

// Transposed weights: [l][kkp][ga(ih_r,ih_z,ih_n,hh_r,hh_z,hh_n)][tid] float4,
// tid = grp*128 + u -> (unit u, K-quarter grp).
__device__ float4 g_wt[LAYERS * KKQ * 6 * NTHR];

__global__ void prep_kernel(const float* __restrict__ wih,
                            const float* __restrict__ whh) {
  int idx = blockIdx.x * blockDim.x + threadIdx.x;
  if (idx >= LAYERS * KKQ * 6 * NTHR) return;
  int t   = idx % NTHR;
  int ga  = (idx / NTHR) % 6;
  int kkp = (idx / (NTHR * 6)) % KKQ;
  int l   = idx / (NTHR * 6 * KKQ);
  int g   = ga % 3, arr = ga / 3;
  int u   = t & 127, grp = t >> 7;
  int k4  = grp * KKQ + kkp;
  const float* src = (arr ? whh : wih) + (l * G3 + g * 128 + u) * H + k4 * 4;
  g_wt[idx] = *reinterpret_cast<const float4*>(src);
}

__device__ __forceinline__ void ffma2(ull& a, ull w, ull x) {
  asm("fma.rn.f32x2 %0, %1, %2, %0;" : "+l"(a) : "l"(w), "l"(x));
}
__device__ __forceinline__ void fadd2(ull& a, ull b) {
  asm("add.rn.f32x2 %0, %0, %1;" : "+l"(a) : "l"(b));
}
__device__ __forceinline__ ull dup2(float w) {
  ull r;
  asm("mov.b64 %0, {%1, %1};" : "=l"(r) : "f"(w));
  return r;
}
__device__ __forceinline__ float2 unpk(ull v) {
  float lo, hi;
  asm("mov.b64 {%0, %1}, %2;" : "=f"(lo), "=f"(hi) : "l"(v));
  return make_float2(lo, hi);
}
__device__ __forceinline__ ull pack2(float lo, float hi) {
  ull r;
  asm("mov.b64 %0, {%1, %2};" : "=l"(r) : "f"(lo), "f"(hi));
  return r;
}
__device__ __forceinline__ float sigm(float x) {
  return __fdividef(1.0f, 1.0f + __expf(-x));
}
__device__ __forceinline__ float tanh_fast(float v) {
  float a = fabsf(v);
  float e = __expf(-2.0f * a);
  float r = __fdividef(1.0f - e, 1.0f + e);
  return copysignf(r, v);
}
__device__ __forceinline__ float comp(const float4& v, int e) {
  return e == 0 ? v.x : e == 1 ? v.y : e == 2 ? v.z : v.w;
}

// Combine batch-pair Q: add 3 partner contributions, run GRU gate math,
// write new hidden state. Q compile-time -> constant offsets everywhere.
template <int Q>
__device__ __forceinline__ void combine_pair(ull r2, ull z2, ull nx2, ull nh2,
                                             const ull* __restrict__ sp, int u,
                                             float brz_r, float brz_z,
                                             float bn_x, float bn_h,
                                             float* __restrict__ hl,
                                             float* __restrict__ sx) {
#pragma unroll
  for (int c = 0; c < 3; c++) {
    const ull* base = sp + (Q * 3 + c) * 4 * 128 + u;
    fadd2(r2,  base[0]);
    fadd2(z2,  base[128]);
    fadd2(nx2, base[256]);
    fadd2(nh2, base[384]);
  }
  float2 rr = unpk(r2), zz = unpk(z2), xx = unpk(nx2), hh = unpk(nh2);
  float hp0 = hl[u * 8 + 2 * Q], hp1 = hl[u * 8 + 2 * Q + 1];
  float r0 = sigm(rr.x + brz_r), z0 = sigm(zz.x + brz_z);
  float n0 = tanh_fast(xx.x + bn_x + r0 * (hh.x + bn_h));
  float h0 = fmaf(z0, hp0 - n0, n0);
  float r1 = sigm(rr.y + brz_r), z1 = sigm(zz.y + brz_z);
  float n1 = tanh_fast(xx.y + bn_x + r1 * (hh.y + bn_h));
  float h1 = fmaf(z1, hp1 - n1, n1);
  ull o = pack2(h0, h1);
  *reinterpret_cast<ull*>(hl + u * 8 + 2 * Q) = o;
  *reinterpret_cast<ull*>(sx + u * 8 + 2 * Q) = o;
}

__global__ void __launch_bounds__(NTHR, 1)
gru_kernel(const float* __restrict__ hiddens,
           const float* __restrict__ b_ih,
           const float* __restrict__ b_hh,
           const float* __restrict__ fc_w,
           const float* __restrict__ fc_b,
           float* __restrict__ out) {
  extern __shared__ __align__(16) char dsm[];
  float* s_x   = reinterpret_cast<float*>(dsm + SMEM_X);
  float* s_h   = reinterpret_cast<float*>(dsm + SMEM_H);
  ull*   s_p   = reinterpret_cast<ull*>(dsm + SMEM_P);
  float* s_fcw = reinterpret_cast<float*>(dsm + SMEM_FCW);
  float* s_fcb = reinterpret_cast<float*>(dsm + SMEM_FCB);

  const int tid = threadIdx.x;
  const int u   = tid & 127;
  const int grp = tid >> 7;
  const int b0  = blockIdx.x * BC;

  // Biases for hidden unit u (r,z summed; n split).
  float brz_r[LAYERS], brz_z[LAYERS], bn_x[LAYERS], bn_h[LAYERS];
#pragma unroll
  for (int l = 0; l < LAYERS; l++) {
    brz_r[l] = b_ih[l * G3 + u]       + b_hh[l * G3 + u];
    brz_z[l] = b_ih[l * G3 + 128 + u] + b_hh[l * G3 + 128 + u];
    bn_x[l]  = b_ih[l * G3 + 256 + u];
    bn_h[l]  = b_hh[l * G3 + 256 + u];
  }
  if (tid < 256) s_fcw[tid] = fc_w[tid];
  if (tid < 2)   s_fcb[tid] = fc_b[tid];

  // h init: hiddens[b][l][k] -> s_h[l][k][b]
  for (int i = tid; i < LAYERS * H * BC; i += NTHR) {
    int l = i >> 10, rem = i & 1023, k = rem >> 3, b = rem & 7;
    s_h[i] = hiddens[(b0 + b) * (LAYERS * H) + l * H + k];
  }
  for (int i = tid; i < H * BC; i += NTHR) s_x[i] = 0.0f;
  __syncthreads();

  for (int t = 0; t < T; t++) {
#pragma unroll 1
    for (int l = 0; l < LAYERS; l++) {
      const float* __restrict__  xb = s_x + grp * 256;         // K-quarter
      float* __restrict__        hl = s_h + l * (H * BC);
      const float* __restrict__  hb = hl + grp * 256;
      const float4* __restrict__ wp = g_wt + l * (KKQ * 6 * NTHR) + tid;

      ull acc[3][2][4];
#pragma unroll
      for (int g = 0; g < 3; g++)
#pragma unroll
        for (int a = 0; a < 2; a++)
#pragma unroll
          for (int q = 0; q < 4; q++) acc[g][a][q] = 0ull;

      // Double-buffered weights: wn holds kkp+1 while kkp computes.
      float4 wv[6], wn[6];
#pragma unroll
      for (int i = 0; i < 6; i++) wn[i] = wp[i * NTHR];

#pragma unroll
      for (int kkp = 0; kkp < KKQ; kkp++) {
#pragma unroll
        for (int i = 0; i < 6; i++) wv[i] = wn[i];
        if (kkp < KKQ - 1) {
#pragma unroll
          for (int i = 0; i < 6; i++)
            wn[i] = wp[((kkp + 1) * 6 + i) * NTHR];
        }
#pragma unroll
        for (int e = 0; e < 4; e++) {
          int k8 = (kkp * 4 + e) * 8;
          ulonglong2 xv0 = *reinterpret_cast<const ulonglong2*>(xb + k8);
          ulonglong2 xv1 = *reinterpret_cast<const ulonglong2*>(xb + k8 + 4);
          ulonglong2 hv0 = *reinterpret_cast<const ulonglong2*>(hb + k8);
          ulonglong2 hv1 = *reinterpret_cast<const ulonglong2*>(hb + k8 + 4);
#pragma unroll
          for (int g = 0; g < 3; g++) {
            ull dx = dup2(comp(wv[g], e));          // W_ih
            ffma2(acc[g][0][0], dx, xv0.x);
            ffma2(acc[g][0][1], dx, xv0.y);
            ffma2(acc[g][0][2], dx, xv1.x);
            ffma2(acc[g][0][3], dx, xv1.y);
            ull dh = dup2(comp(wv[3 + g], e));      // W_hh
            ffma2(acc[g][1][0], dh, hv0.x);
            ffma2(acc[g][1][1], dh, hv0.y);
            ffma2(acc[g][1][2], dh, hv1.x);
            ffma2(acc[g][1][3], dh, hv1.y);
          }
        }
      }

      // r,z: arrays summed now (only the total matters).
      ull rzr[4], rzz[4];
#pragma unroll
      for (int q = 0; q < 4; q++) {
        rzr[q] = acc[0][0][q]; fadd2(rzr[q], acc[0][1][q]);
        rzz[q] = acc[1][0][q]; fadd2(rzz[q], acc[1][1][q]);
      }

      // Store partials for the 3 batch-pairs this group does not own.
#pragma unroll
      for (int q = 0; q < 4; q++) {
        if (q == grp) continue;                    // runtime guard, const q
        int c = grp - (grp > q ? 1 : 0);
        ull* base = s_p + (q * 3 + c) * 4 * 128 + u;
        base[0]   = rzr[q];
        base[128] = rzz[q];
        base[256] = acc[2][0][q];
        base[384] = acc[2][1][q];
      }
      __syncthreads();

      if (grp == 0)
        combine_pair<0>(rzr[0], rzz[0], acc[2][0][0], acc[2][1][0], s_p, u,
                        brz_r[l], brz_z[l], bn_x[l], bn_h[l], hl, s_x);
      else if (grp == 1)
        combine_pair<1>(rzr[1], rzz[1], acc[2][0][1], acc[2][1][1], s_p, u,
                        brz_r[l], brz_z[l], bn_x[l], bn_h[l], hl, s_x);
      else if (grp == 2)
        combine_pair<2>(rzr[2], rzz[2], acc[2][0][2], acc[2][1][2], s_p, u,
                        brz_r[l], brz_z[l], bn_x[l], bn_h[l], hl, s_x);
      else
        combine_pair<3>(rzr[3], rzz[3], acc[2][0][3], acc[2][1][3], s_p, u,
                        brz_r[l], brz_z[l], bn_x[l], bn_h[l], hl, s_x);
      __syncthreads();

      // fc head on top-layer output: 16 outputs (2 out x 8 batch) x 16 lanes.
      if (l == 2 && tid < 256) {
        int oid = tid >> 4, s = tid & 15;
        int o = oid & 1, b = oid >> 1;
        float p = 0.0f;
#pragma unroll
        for (int m = 0; m < 8; m++)
          p = fmaf(s_fcw[o * H + s * 8 + m], s_x[(s * 8 + m) * 8 + b], p);
        p += __shfl_down_sync(0xffffffffu, p, 8, 16);
        p += __shfl_down_sync(0xffffffffu, p, 4, 16);
        p += __shfl_down_sync(0xffffffffu, p, 2, 16);
        p += __shfl_down_sync(0xffffffffu, p, 1, 16);
        if (s == 0) out[((b0 + b) * T + t) * 2 + o] = p + s_fcb[o];
      }
      // fc reads of s_x finish before the next cell's combine rewrites s_x
      // (that rewrite sits behind the next cell's exchange __syncthreads()).
    }
  }
}

extern "C" void kernel_launch(void* const* d_in, const int* in_sizes, int n_in,
                              void* d_out, int out_size) {
  (void)in_sizes; (void)n_in; (void)out_size;
  const float* hiddens = (const float*)d_in[0];
  const float* W_ih    = (const float*)d_in[1];
  const float* W_hh    = (const float*)d_in[2];
  const float* b_ih    = (const float*)d_in[3];
  const float* b_hh    = (const float*)d_in[4];
  const float* fc_w    = (const float*)d_in[5];
  const float* fc_b    = (const float*)d_in[6];
  float* out = (float*)d_out;

  cudaFuncSetAttribute(gru_kernel, cudaFuncAttributeMaxDynamicSharedMemorySize,
                       SMEM_TOTAL);

  const int prep_elems = LAYERS * KKQ * 6 * NTHR;
  prep_kernel<<<(prep_elems + 255) / 256, 256>>>(W_ih, W_hh);
  gru_kernel<<<NBLK, NTHR, SMEM_TOTAL>>>(hiddens, b_ih, b_hh, fc_w, fc_b, out);
}